// round 1
// baseline (speedup 1.0000x reference)
#include <cuda_runtime.h>
#include <cstdint>

#define NN 50000
#define NE 1600000
#define D  128
#define DIN 384

// ---------------- scratch (device globals; no allocation allowed) ----------
__device__ int   g_counts[NN];
__device__ int   g_offsets[NN];
__device__ int   g_cursor[NN];
__device__ int   g_edge_ids[NE];
__device__ float g_agg[(size_t)NN * D];
__device__ float g_tmp[(size_t)NN * D];
__device__ float g_c0[D];

// ---------------- CSR build -------------------------------------------------
__global__ void k_zero_counts() {
    int i = blockIdx.x * blockDim.x + threadIdx.x;
    if (i < NN) g_counts[i] = 0;
}

__global__ void k_count(const int* __restrict__ dst) {
    int e = blockIdx.x * blockDim.x + threadIdx.x;
    if (e < NE) atomicAdd(&g_counts[dst[e]], 1);
}

// single-block scan over 50000 counts -> exclusive offsets (+cursor copy)
__global__ void k_scan() {
    __shared__ int s[1024];
    const int T = 1024;
    const int chunk = (NN + T - 1) / T;      // 49
    int t = threadIdx.x;
    int base = t * chunk;
    int local = 0;
    for (int i = 0; i < chunk; i++) {
        int idx = base + i;
        if (idx < NN) local += g_counts[idx];
    }
    s[t] = local;
    __syncthreads();
    for (int d = 1; d < T; d <<= 1) {
        int add = (t >= d) ? s[t - d] : 0;
        __syncthreads();
        s[t] += add;
        __syncthreads();
    }
    int run = (t == 0) ? 0 : s[t - 1];
    for (int i = 0; i < chunk; i++) {
        int idx = base + i;
        if (idx < NN) {
            g_offsets[idx] = run;
            g_cursor[idx]  = run;
            run += g_counts[idx];
        }
    }
}

__global__ void k_fill(const int* __restrict__ dst) {
    int e = blockIdx.x * blockDim.x + threadIdx.x;
    if (e < NE) {
        int pos = atomicAdd(&g_cursor[dst[e]], 1);
        g_edge_ids[pos] = e;
    }
}

// ---------------- warp-per-node segment mean (atomic-free gather) ----------
__global__ void k_aggregate(const float* __restrict__ edge_attrs) {
    int warp = threadIdx.x >> 5;
    int lane = threadIdx.x & 31;
    int node = blockIdx.x * (blockDim.x >> 5) + warp;
    if (node >= NN) return;

    int start = g_offsets[node];
    int deg   = g_counts[node];

    float4 a0 = make_float4(0.f, 0.f, 0.f, 0.f);
    float4 a1 = make_float4(0.f, 0.f, 0.f, 0.f);
    int i = 0;
    for (; i + 1 < deg; i += 2) {
        int e0 = g_edge_ids[start + i];
        int e1 = g_edge_ids[start + i + 1];
        float4 v0 = __ldg((const float4*)(edge_attrs + (size_t)e0 * D) + lane);
        float4 v1 = __ldg((const float4*)(edge_attrs + (size_t)e1 * D) + lane);
        a0.x += v0.x; a0.y += v0.y; a0.z += v0.z; a0.w += v0.w;
        a1.x += v1.x; a1.y += v1.y; a1.z += v1.z; a1.w += v1.w;
    }
    if (i < deg) {
        int e0 = g_edge_ids[start + i];
        float4 v0 = __ldg((const float4*)(edge_attrs + (size_t)e0 * D) + lane);
        a0.x += v0.x; a0.y += v0.y; a0.z += v0.z; a0.w += v0.w;
    }
    float inv = (deg > 0) ? (1.0f / (float)deg) : 0.0f;
    float4 r;
    r.x = (a0.x + a1.x) * inv;
    r.y = (a0.y + a1.y) * inv;
    r.z = (a0.z + a1.z) * inv;
    r.w = (a0.w + a1.w) * inv;
    *((float4*)(g_agg + (size_t)node * D) + lane) = r;
}

// ---------------- c0 = global_attr @ W1[256:384,:] + b1 --------------------
__global__ void k_c0(const float* __restrict__ gattr,
                     const float* __restrict__ W1,
                     const float* __restrict__ b1) {
    int j = threadIdx.x;  // 128
    float s = b1[j];
    for (int k = 0; k < 128; k++)
        s += gattr[k] * W1[(size_t)(256 + k) * D + j];
    g_c0[j] = s;
}

// ---------------- fp32x2 tiled GEMM -----------------------------------------
// C[m,j] = act( sum_{k<KT} Asel[m, k%128] * W[k, j] + bias[j] )
// Asel = A1 for k<128, A2 for k>=128.  BM=BN=128, BK=16, 256 threads, 8x8 tile
// accumulated as 8x4 packed f32x2 via fma.rn.f32x2 (2x fp32 rate).
template <bool RELU>
__global__ void __launch_bounds__(256, 2)
k_gemm(const float* __restrict__ A1, const float* __restrict__ A2,
       const float* __restrict__ W,  const float* __restrict__ bias,
       float* __restrict__ C, int M, int KT) {
    __shared__ float As[16][128];
    __shared__ float Bs[16][128];

    int tid = threadIdx.x;
    int m0  = blockIdx.x * 128;
    int tm  = (tid >> 4) << 3;   // 0..120
    int tn  = (tid & 15) << 3;   // 0..120

    unsigned long long acc[8][4];
#pragma unroll
    for (int r = 0; r < 8; r++)
#pragma unroll
        for (int p = 0; p < 4; p++) acc[r][p] = 0ULL;

    for (int kb = 0; kb < KT; kb += 16) {
        const float* A = (kb < 128) ? A1 : A2;
        int kcol = kb & 127;

        // A tile: 128 rows x 16 k, stored transposed As[k][m]
        {
            int ar = tid >> 2;            // 0..63
            int ak = (tid & 3) << 2;      // 0,4,8,12
#pragma unroll
            for (int h = 0; h < 2; h++) {
                int mrow = ar + h * 64;
                int m = m0 + mrow;
                float4 v = make_float4(0.f, 0.f, 0.f, 0.f);
                if (m < M) v = *(const float4*)(A + (size_t)m * D + kcol + ak);
                As[ak + 0][mrow] = v.x;
                As[ak + 1][mrow] = v.y;
                As[ak + 2][mrow] = v.z;
                As[ak + 3][mrow] = v.w;
            }
        }
        // B tile: 16 rows x 128 cols, direct
        {
#pragma unroll
            for (int h = 0; h < 2; h++) {
                int pos = tid + h * 256;      // 0..511 float4 slots
                int bk  = pos >> 5;           // 0..15
                int bj  = (pos & 31) << 2;    // 0..124
                *(float4*)&Bs[bk][bj] =
                    *(const float4*)(W + (size_t)(kb + bk) * D + bj);
            }
        }
        __syncthreads();

#pragma unroll
        for (int kk = 0; kk < 16; kk++) {
            float a[8];
            *(float4*)&a[0] = *(const float4*)&As[kk][tm];
            *(float4*)&a[4] = *(const float4*)&As[kk][tm + 4];
            unsigned long long b[4];
            float4 bv0 = *(const float4*)&Bs[kk][tn];
            float4 bv1 = *(const float4*)&Bs[kk][tn + 4];
            b[0] = *(unsigned long long*)&bv0.x;
            b[1] = *(unsigned long long*)&bv0.z;
            b[2] = *(unsigned long long*)&bv1.x;
            b[3] = *(unsigned long long*)&bv1.z;
#pragma unroll
            for (int r = 0; r < 8; r++) {
                unsigned long long a2;
                asm("mov.b64 %0, {%1, %1};" : "=l"(a2) : "f"(a[r]));
#pragma unroll
                for (int p = 0; p < 4; p++) {
                    asm("fma.rn.f32x2 %0, %1, %2, %0;"
                        : "+l"(acc[r][p]) : "l"(a2), "l"(b[p]));
                }
            }
        }
        __syncthreads();
    }

    // epilogue
    float bj[8];
    *(float4*)&bj[0] = *(const float4*)(bias + tn);
    *(float4*)&bj[4] = *(const float4*)(bias + tn + 4);
#pragma unroll
    for (int r = 0; r < 8; r++) {
        int m = m0 + tm + r;
        if (m < M) {
            float out[8];
#pragma unroll
            for (int p = 0; p < 4; p++) {
                float2 f = *(float2*)&acc[r][p];
                out[2 * p + 0] = f.x + bj[2 * p + 0];
                out[2 * p + 1] = f.y + bj[2 * p + 1];
            }
            if (RELU) {
#pragma unroll
                for (int q = 0; q < 8; q++) out[q] = fmaxf(out[q], 0.f);
            }
            *(float4*)(C + (size_t)m * D + tn)     = *(float4*)&out[0];
            *(float4*)(C + (size_t)m * D + tn + 4) = *(float4*)&out[4];
        }
    }
}

// ---------------- launch -----------------------------------------------------
extern "C" void kernel_launch(void* const* d_in, const int* in_sizes, int n_in,
                              void* d_out, int out_size) {
    const float* edge_attrs = (const float*)d_in[0];
    const float* node_attrs = (const float*)d_in[1];
    const float* gattr      = (const float*)d_in[2];
    const float* W1         = (const float*)d_in[3];
    const float* b1         = (const float*)d_in[4];
    const float* W2         = (const float*)d_in[5];
    const float* b2         = (const float*)d_in[6];
    const int*   edge_dst   = (const int*)d_in[7];
    float*       out        = (float*)d_out;

    float* agg_p; cudaGetSymbolAddress((void**)&agg_p, g_agg);
    float* tmp_p; cudaGetSymbolAddress((void**)&tmp_p, g_tmp);
    float* c0_p;  cudaGetSymbolAddress((void**)&c0_p,  g_c0);

    k_zero_counts<<<(NN + 255) / 256, 256>>>();
    k_count<<<(NE + 255) / 256, 256>>>(edge_dst);
    k_scan<<<1, 1024>>>();
    k_fill<<<(NE + 255) / 256, 256>>>(edge_dst);
    k_aggregate<<<(NN + 7) / 8, 256>>>(edge_attrs);
    k_c0<<<1, 128>>>(gattr, W1, b1);

    int mb = (NN + 127) / 128;
    k_gemm<true ><<<mb, 256>>>(agg_p, node_attrs, W1, c0_p, tmp_p, NN, 256);
    k_gemm<false><<<mb, 256>>>(tmp_p, nullptr, W2, b2, out, NN, 128);
}

// round 3
// speedup vs baseline: 1.1689x; 1.1689x over previous
#include <cuda_runtime.h>
#include <cuda_bf16.h>
#include <cstdint>

#define NN 50000
#define NE 1600000
#define D  128

// ---------------- scratch (device globals; no allocation allowed) ----------
__device__ int   g_counts[NN];
__device__ int   g_offsets[NN];
__device__ int   g_cursor[NN];
__device__ int   g_edge_ids[NE];
__device__ float g_agg[(size_t)NN * D];
__device__ float g_c0[D];
// frag-major pre-split weights: {hi0, hi1, lo0, lo1} per lane per (ntile,ktile)
__device__ uint4 g_W1f[8 * 16 * 2 * 32];   // K=256: 8 kblocks x 16 ntiles x 2 kt x 32 lanes
__device__ uint4 g_W2f[16 * 8 * 32];       // K=128: 16 ntiles x 8 ktiles x 32 lanes

// ---------------- helpers ----------------------------------------------------
__device__ __forceinline__ uint32_t pack_bf16(float x0, float x1) {
    __nv_bfloat162 h = __floats2bfloat162_rn(x0, x1);  // .x = x0 (low half)
    return *(uint32_t*)&h;
}
__device__ __forceinline__ void split_pair(float x0, float x1,
                                           uint32_t& hi, uint32_t& lo) {
    __nv_bfloat16 h0 = __float2bfloat16_rn(x0);
    __nv_bfloat16 h1 = __float2bfloat16_rn(x1);
    float l0 = x0 - __bfloat162float(h0);
    float l1 = x1 - __bfloat162float(h1);
    __nv_bfloat162 hp; hp.x = h0; hp.y = h1;
    hi = *(uint32_t*)&hp;
    lo = pack_bf16(l0, l1);
}
__device__ __forceinline__ void mma_bf16(float* d, uint32_t a0, uint32_t a1,
                                         uint32_t a2, uint32_t a3,
                                         uint32_t b0, uint32_t b1) {
    asm volatile(
        "mma.sync.aligned.m16n8k16.row.col.f32.bf16.bf16.f32 "
        "{%0,%1,%2,%3}, {%4,%5,%6,%7}, {%8,%9}, {%0,%1,%2,%3};"
        : "+f"(d[0]), "+f"(d[1]), "+f"(d[2]), "+f"(d[3])
        : "r"(a0), "r"(a1), "r"(a2), "r"(a3), "r"(b0), "r"(b1));
}

// ---------------- CSR build -------------------------------------------------
__global__ void k_zero_counts() {
    int i = blockIdx.x * blockDim.x + threadIdx.x;
    if (i < NN) g_counts[i] = 0;
}
__global__ void k_count(const int* __restrict__ dst) {
    int e = blockIdx.x * blockDim.x + threadIdx.x;
    if (e < NE) atomicAdd(&g_counts[dst[e]], 1);
}
__global__ void k_scan() {
    __shared__ int s[1024];
    const int T = 1024;
    const int chunk = (NN + T - 1) / T;
    int t = threadIdx.x;
    int base = t * chunk;
    int local = 0;
    for (int i = 0; i < chunk; i++) {
        int idx = base + i;
        if (idx < NN) local += g_counts[idx];
    }
    s[t] = local;
    __syncthreads();
    for (int d = 1; d < T; d <<= 1) {
        int add = (t >= d) ? s[t - d] : 0;
        __syncthreads();
        s[t] += add;
        __syncthreads();
    }
    int run = (t == 0) ? 0 : s[t - 1];
    for (int i = 0; i < chunk; i++) {
        int idx = base + i;
        if (idx < NN) {
            g_offsets[idx] = run;
            g_cursor[idx]  = run;
            run += g_counts[idx];
        }
    }
}
__global__ void k_fill(const int* __restrict__ dst) {
    int e = blockIdx.x * blockDim.x + threadIdx.x;
    if (e < NE) {
        int pos = atomicAdd(&g_cursor[dst[e]], 1);
        g_edge_ids[pos] = e;
    }
}

// ---------------- warp-per-node segment mean --------------------------------
__global__ void k_aggregate(const float* __restrict__ edge_attrs) {
    int warp = threadIdx.x >> 5;
    int lane = threadIdx.x & 31;
    int node = blockIdx.x * (blockDim.x >> 5) + warp;
    if (node >= NN) return;

    int start = g_offsets[node];
    int deg   = g_counts[node];

    float4 a0 = make_float4(0.f, 0.f, 0.f, 0.f);
    float4 a1 = make_float4(0.f, 0.f, 0.f, 0.f);
    int i = 0;
    for (; i + 1 < deg; i += 2) {
        int e0 = g_edge_ids[start + i];
        int e1 = g_edge_ids[start + i + 1];
        float4 v0 = __ldg((const float4*)(edge_attrs + (size_t)e0 * D) + lane);
        float4 v1 = __ldg((const float4*)(edge_attrs + (size_t)e1 * D) + lane);
        a0.x += v0.x; a0.y += v0.y; a0.z += v0.z; a0.w += v0.w;
        a1.x += v1.x; a1.y += v1.y; a1.z += v1.z; a1.w += v1.w;
    }
    if (i < deg) {
        int e0 = g_edge_ids[start + i];
        float4 v0 = __ldg((const float4*)(edge_attrs + (size_t)e0 * D) + lane);
        a0.x += v0.x; a0.y += v0.y; a0.z += v0.z; a0.w += v0.w;
    }
    float inv = (deg > 0) ? (1.0f / (float)deg) : 0.0f;
    float4 r;
    r.x = (a0.x + a1.x) * inv;
    r.y = (a0.y + a1.y) * inv;
    r.z = (a0.z + a1.z) * inv;
    r.w = (a0.w + a1.w) * inv;
    *((float4*)(g_agg + (size_t)node * D) + lane) = r;
}

// ---------------- c0 = global_attr @ W1[256:384,:] + b1 --------------------
__global__ void k_c0(const float* __restrict__ gattr,
                     const float* __restrict__ W1,
                     const float* __restrict__ b1) {
    int j = threadIdx.x;
    float s = b1[j];
    for (int k = 0; k < 128; k++)
        s += gattr[k] * W1[(size_t)(256 + k) * D + j];
    g_c0[j] = s;
}

// ---------------- weight prep: bf16 split into frag-major layout -----------
__global__ void k_prep(const float* __restrict__ W1, const float* __restrict__ W2) {
    int i = blockIdx.x * blockDim.x + threadIdx.x;
    if (i < 8192) {
        int lane = i & 31, ntile = (i >> 5) & 15, ktile = i >> 9;  // ktile 0..15
        int g = lane >> 2, c = lane & 3;
        int n = ntile * 8 + g;
        int k0 = ktile * 16 + 2 * c;
        float w0 = W1[(size_t)(k0 + 0) * D + n];
        float w1 = W1[(size_t)(k0 + 1) * D + n];
        float w8 = W1[(size_t)(k0 + 8) * D + n];
        float w9 = W1[(size_t)(k0 + 9) * D + n];
        uint4 o;
        split_pair(w0, w1, o.x, o.z);
        split_pair(w8, w9, o.y, o.w);
        int idx = (((ktile >> 1) * 16 + ntile) * 2 + (ktile & 1)) * 32 + lane;
        g_W1f[idx] = o;
    } else if (i < 8192 + 4096) {
        int j = i - 8192;
        int lane = j & 31, ntile = (j >> 5) & 15, ktile = j >> 9;  // ktile 0..7
        int g = lane >> 2, c = lane & 3;
        int n = ntile * 8 + g;
        int k0 = ktile * 16 + 2 * c;
        float w0 = W2[(size_t)(k0 + 0) * D + n];
        float w1 = W2[(size_t)(k0 + 1) * D + n];
        float w8 = W2[(size_t)(k0 + 8) * D + n];
        float w9 = W2[(size_t)(k0 + 9) * D + n];
        uint4 o;
        split_pair(w0, w1, o.x, o.z);
        split_pair(w8, w9, o.y, o.w);
        g_W2f[(ntile * 8 + ktile) * 32 + lane] = o;
    }
}

// ---------------- fused 2-layer MLP with mma.sync bf16-split ----------------
// smem: A stages 2x16KB @0, B stages 2x16KB @32KB, A2 64KB @64KB, B2 64KB @128KB
#define SM_SA(s) ((s) * 16384)
#define SM_SB(s) (32768 + (s) * 16384)
#define SM_A2 65536
#define SM_B2 131072
#define MLP_SMEM 196608

__device__ __forceinline__ void mma_block(const char* sm, uint32_t abase,
                                          uint32_t bbase, int KT, int kt,
                                          int wm, int wn, int lane,
                                          float Dm[2][8][4]) {
    uint4 ah[2], al[2];
#pragma unroll
    for (int mt = 0; mt < 2; mt++) {
        const uint4* p = (const uint4*)(sm + abase +
            (uint32_t)((((wm * 2 + mt) * KT + kt) * 32 + lane) * 32));
        ah[mt] = p[0];
        al[mt] = p[1];
    }
#pragma unroll
    for (int nt = 0; nt < 8; nt++) {
        uint4 b = *(const uint4*)(sm + bbase +
            (uint32_t)((((wn * 8 + nt) * KT + kt) * 32 + lane) * 16));
#pragma unroll
        for (int mt = 0; mt < 2; mt++) {
            mma_bf16(Dm[mt][nt], ah[mt].x, ah[mt].y, ah[mt].z, ah[mt].w, b.x, b.y);
            mma_bf16(Dm[mt][nt], ah[mt].x, ah[mt].y, ah[mt].z, ah[mt].w, b.z, b.w);
            mma_bf16(Dm[mt][nt], al[mt].x, al[mt].y, al[mt].z, al[mt].w, b.x, b.y);
        }
    }
}

__global__ void __launch_bounds__(256, 1)
k_mlp(const float* __restrict__ agg, const float* __restrict__ node,
      const float* __restrict__ c0, const float* __restrict__ b2,
      float* __restrict__ out) {
    extern __shared__ char sm[];
    int tid = threadIdx.x, lane = tid & 31, wid = tid >> 5;
    int wm = wid >> 1, wn = wid & 1;
    int m0 = blockIdx.x * 128;

    // staging mapping: thread -> (row, k16-segment)
    int srow = tid >> 1;          // 0..127
    int skt  = tid & 1;           // 0/1
    int smt  = srow >> 4;
    int slan = (srow & 7) * 4;
    int srh  = (srow >> 3) & 1;
    int gm   = m0 + srow;
    bool mok = (gm < NN);

    float D1[2][8][4];
#pragma unroll
    for (int a = 0; a < 2; a++)
#pragma unroll
        for (int b = 0; b < 8; b++)
#pragma unroll
            for (int q = 0; q < 4; q++) D1[a][b][q] = 0.f;

    float4 va[4];
    uint4  vb[4];
    // prologue: load stage 0
    {
        const float* src = agg;
        int kc = skt * 16;
#pragma unroll
        for (int q = 0; q < 4; q++)
            va[q] = mok ? *(const float4*)(src + (size_t)gm * D + kc + q * 4)
                        : make_float4(0.f, 0.f, 0.f, 0.f);
#pragma unroll
        for (int q = 0; q < 4; q++) vb[q] = g_W1f[tid + q * 256];
    }

    for (int s = 0; s < 8; s++) {
        int buf = s & 1;
        // store staged regs into smem (A: convert+split, B: raw copy)
        {
            float xs[16];
#pragma unroll
            for (int q = 0; q < 4; q++) {
                xs[q * 4 + 0] = va[q].x; xs[q * 4 + 1] = va[q].y;
                xs[q * 4 + 2] = va[q].z; xs[q * 4 + 3] = va[q].w;
            }
            uint32_t abase = SM_SA(buf) + (uint32_t)(((smt * 2 + skt) * 32) * 32);
#pragma unroll
            for (int p = 0; p < 8; p++) {
                uint32_t hi, lo;
                split_pair(xs[2 * p], xs[2 * p + 1], hi, lo);
                int c = p & 3, j = p >> 2;
                uint32_t off = abase + (uint32_t)((slan + c) * 32 + (srh + 2 * j) * 4);
                *(uint32_t*)(sm + off)      = hi;
                *(uint32_t*)(sm + off + 16) = lo;
            }
            uint4* bdst = (uint4*)(sm + SM_SB(buf));
#pragma unroll
            for (int q = 0; q < 4; q++) bdst[tid + q * 256] = vb[q];
        }
        __syncthreads();
        if (s == 0) {  // copy W2 frags into B2 (latency overlaps early compute)
            uint4* b2dst = (uint4*)(sm + SM_B2);
            for (int q = 0; q < 16; q++) b2dst[tid + q * 256] = g_W2f[tid + q * 256];
        }
        if (s < 7) {  // prefetch next stage
            const float* src = (s + 1 < 4) ? agg : node;
            int kc = ((s + 1) & 3) * 32 + skt * 16;
#pragma unroll
            for (int q = 0; q < 4; q++)
                va[q] = mok ? *(const float4*)(src + (size_t)gm * D + kc + q * 4)
                            : make_float4(0.f, 0.f, 0.f, 0.f);
#pragma unroll
            for (int q = 0; q < 4; q++) vb[q] = g_W1f[(s + 1) * 1024 + tid + q * 256];
        }
        // compute the 2 k16-steps of this stage
        mma_block(sm, SM_SA(buf), SM_SB(buf), 2, 0, wm, wn, lane, D1);
        mma_block(sm, SM_SA(buf), SM_SB(buf), 2, 1, wm, wn, lane, D1);
    }

    // epilogue-1: h = relu(D1 + c0) -> frag-major A2 (bf16 hi/lo)
    {
        int c = lane & 3;
#pragma unroll
        for (int mt = 0; mt < 2; mt++) {
#pragma unroll
            for (int nt = 0; nt < 8; nt++) {
                int col = wn * 64 + nt * 8 + 2 * c;
                float2 cv = *(const float2*)(c0 + col);
                float h0 = fmaxf(D1[mt][nt][0] + cv.x, 0.f);
                float h1 = fmaxf(D1[mt][nt][1] + cv.y, 0.f);
                float h2 = fmaxf(D1[mt][nt][2] + cv.x, 0.f);
                float h3 = fmaxf(D1[mt][nt][3] + cv.y, 0.f);
                uint32_t hi0, lo0, hi1, lo1;
                split_pair(h0, h1, hi0, lo0);
                split_pair(h2, h3, hi1, lo1);
                int mtile2 = wm * 2 + mt;
                int ktile2 = wn * 4 + (nt >> 1);
                int j2 = nt & 1;
                uint32_t base = SM_A2 +
                    (uint32_t)(((mtile2 * 8 + ktile2) * 32 + lane) * 32);
                *(uint32_t*)(sm + base + (0 + 2 * j2) * 4)      = hi0;
                *(uint32_t*)(sm + base + (0 + 2 * j2) * 4 + 16) = lo0;
                *(uint32_t*)(sm + base + (1 + 2 * j2) * 4)      = hi1;
                *(uint32_t*)(sm + base + (1 + 2 * j2) * 4 + 16) = lo1;
            }
        }
    }
    __syncthreads();

    // layer 2: K=128, all smem-resident
    float D2[2][8][4];
#pragma unroll
    for (int a = 0; a < 2; a++)
#pragma unroll
        for (int b = 0; b < 8; b++)
#pragma unroll
            for (int q = 0; q < 4; q++) D2[a][b][q] = 0.f;
#pragma unroll
    for (int kt = 0; kt < 8; kt++)
        mma_block(sm, SM_A2, SM_B2, 8, kt, wm, wn, lane, D2);

    // epilogue-2: out = D2 + b2
    {
        int c = lane & 3, g = lane >> 2;
#pragma unroll
        for (int mt = 0; mt < 2; mt++) {
            int mrow = m0 + wm * 32 + mt * 16 + g;
#pragma unroll
            for (int nt = 0; nt < 8; nt++) {
                int col = wn * 64 + nt * 8 + 2 * c;
                float2 bv = *(const float2*)(b2 + col);
                if (mrow < NN) {
                    float2 o0 = make_float2(D2[mt][nt][0] + bv.x,
                                            D2[mt][nt][1] + bv.y);
                    *(float2*)(out + (size_t)mrow * D + col) = o0;
                }
                if (mrow + 8 < NN) {
                    float2 o1 = make_float2(D2[mt][nt][2] + bv.x,
                                            D2[mt][nt][3] + bv.y);
                    *(float2*)(out + (size_t)(mrow + 8) * D + col) = o1;
                }
            }
        }
    }
}

// ---------------- launch -----------------------------------------------------
extern "C" void kernel_launch(void* const* d_in, const int* in_sizes, int n_in,
                              void* d_out, int out_size) {
    const float* edge_attrs = (const float*)d_in[0];
    const float* node_attrs = (const float*)d_in[1];
    const float* gattr      = (const float*)d_in[2];
    const float* W1         = (const float*)d_in[3];
    const float* b1         = (const float*)d_in[4];
    const float* W2         = (const float*)d_in[5];
    const float* b2         = (const float*)d_in[6];
    const int*   edge_dst   = (const int*)d_in[7];
    float*       out        = (float*)d_out;

    float* agg_p; cudaGetSymbolAddress((void**)&agg_p, g_agg);
    float* c0_p;  cudaGetSymbolAddress((void**)&c0_p,  g_c0);

    cudaFuncSetAttribute(k_mlp, cudaFuncAttributeMaxDynamicSharedMemorySize,
                         MLP_SMEM);

    k_zero_counts<<<(NN + 255) / 256, 256>>>();
    k_count<<<(NE + 255) / 256, 256>>>(edge_dst);
    k_scan<<<1, 1024>>>();
    k_fill<<<(NE + 255) / 256, 256>>>(edge_dst);
    k_aggregate<<<(NN + 7) / 8, 256>>>(edge_attrs);
    k_c0<<<1, 128>>>(gattr, W1, b1);
    k_prep<<<(8192 + 4096 + 255) / 256, 256>>>(W1, W2);

    int mb = (NN + 127) / 128;
    k_mlp<<<mb, 256, MLP_SMEM>>>(agg_p, node_attrs, c0_p, b2, out);
}

// round 4
// speedup vs baseline: 1.2506x; 1.0699x over previous
#include <cuda_runtime.h>
#include <cuda_bf16.h>
#include <cstdint>

#define NN 50000
#define NE 1600000
#define D  128

// ---------------- scratch (device globals; no allocation allowed) ----------
__device__ int   g_counts[NN];
__device__ int   g_offsets[NN];
__device__ int   g_pos[NE];
__device__ int   g_edge_ids[NE];
__device__ float g_agg[(size_t)NN * D];
__device__ float g_c0[D];
// frag-major pre-split weights: {hi0, hi1, lo0, lo1} per lane per (ntile,ktile)
__device__ uint4 g_W1f[8 * 16 * 2 * 32];   // K=256
__device__ uint4 g_W2f[16 * 8 * 32];       // K=128

// ---------------- helpers ----------------------------------------------------
__device__ __forceinline__ uint32_t pack_bf16(float x0, float x1) {
    __nv_bfloat162 h = __floats2bfloat162_rn(x0, x1);
    return *(uint32_t*)&h;
}
__device__ __forceinline__ void split_pair(float x0, float x1,
                                           uint32_t& hi, uint32_t& lo) {
    __nv_bfloat16 h0 = __float2bfloat16_rn(x0);
    __nv_bfloat16 h1 = __float2bfloat16_rn(x1);
    float l0 = x0 - __bfloat162float(h0);
    float l1 = x1 - __bfloat162float(h1);
    __nv_bfloat162 hp; hp.x = h0; hp.y = h1;
    hi = *(uint32_t*)&hp;
    lo = pack_bf16(l0, l1);
}
__device__ __forceinline__ void mma_bf16(float* d, uint32_t a0, uint32_t a1,
                                         uint32_t a2, uint32_t a3,
                                         uint32_t b0, uint32_t b1) {
    asm volatile(
        "mma.sync.aligned.m16n8k16.row.col.f32.bf16.bf16.f32 "
        "{%0,%1,%2,%3}, {%4,%5,%6,%7}, {%8,%9}, {%0,%1,%2,%3};"
        : "+f"(d[0]), "+f"(d[1]), "+f"(d[2]), "+f"(d[3])
        : "r"(a0), "r"(a1), "r"(a2), "r"(a3), "r"(b0), "r"(b1));
}
__device__ __forceinline__ float4 ldcs4(const float* p) {
    float4 v;
    asm volatile("ld.global.cs.v4.f32 {%0,%1,%2,%3}, [%4];"
                 : "=f"(v.x), "=f"(v.y), "=f"(v.z), "=f"(v.w) : "l"(p));
    return v;
}

// ---------------- fused init: zero counts | c0 | weight prep ----------------
// blocks [0,196): zero counts; block 196: c0; blocks [197,245): prep
__global__ void k_init(const float* __restrict__ gattr,
                       const float* __restrict__ W1,
                       const float* __restrict__ b1,
                       const float* __restrict__ W2) {
    int b = blockIdx.x;
    if (b < 196) {
        int i = b * 256 + threadIdx.x;
        if (i < NN) g_counts[i] = 0;
    } else if (b == 196) {
        if (threadIdx.x < 128) {
            int j = threadIdx.x;
            float s = b1[j];
            for (int k = 0; k < 128; k++)
                s += gattr[k] * W1[(size_t)(256 + k) * D + j];
            g_c0[j] = s;
        }
    } else {
        int i = (b - 197) * 256 + threadIdx.x;
        if (i < 8192) {
            int lane = i & 31, ntile = (i >> 5) & 15, ktile = i >> 9;
            int g = lane >> 2, c = lane & 3;
            int n = ntile * 8 + g;
            int k0 = ktile * 16 + 2 * c;
            float w0 = W1[(size_t)(k0 + 0) * D + n];
            float w1 = W1[(size_t)(k0 + 1) * D + n];
            float w8 = W1[(size_t)(k0 + 8) * D + n];
            float w9 = W1[(size_t)(k0 + 9) * D + n];
            uint4 o;
            split_pair(w0, w1, o.x, o.z);
            split_pair(w8, w9, o.y, o.w);
            int idx = (((ktile >> 1) * 16 + ntile) * 2 + (ktile & 1)) * 32 + lane;
            g_W1f[idx] = o;
        } else if (i < 8192 + 4096) {
            int j = i - 8192;
            int lane = j & 31, ntile = (j >> 5) & 15, ktile = j >> 9;
            int g = lane >> 2, c = lane & 3;
            int n = ntile * 8 + g;
            int k0 = ktile * 16 + 2 * c;
            float w0 = W2[(size_t)(k0 + 0) * D + n];
            float w1 = W2[(size_t)(k0 + 1) * D + n];
            float w8 = W2[(size_t)(k0 + 8) * D + n];
            float w9 = W2[(size_t)(k0 + 9) * D + n];
            uint4 o;
            split_pair(w0, w1, o.x, o.z);
            split_pair(w8, w9, o.y, o.w);
            g_W2f[(ntile * 8 + ktile) * 32 + lane] = o;
        }
    }
}

// ---------------- CSR build (single atomic pass) ----------------------------
__global__ void k_count_pos(const int* __restrict__ dst) {
    int e = blockIdx.x * blockDim.x + threadIdx.x;
    if (e < NE) {
        g_pos[e] = atomicAdd(&g_counts[dst[e]], 1);
    }
}

__global__ void k_scan() {
    __shared__ int s[1024];
    const int T = 1024;
    const int chunk = (NN + T - 1) / T;
    int t = threadIdx.x;
    int base = t * chunk;
    int local = 0;
    for (int i = 0; i < chunk; i++) {
        int idx = base + i;
        if (idx < NN) local += g_counts[idx];
    }
    s[t] = local;
    __syncthreads();
    for (int d = 1; d < T; d <<= 1) {
        int add = (t >= d) ? s[t - d] : 0;
        __syncthreads();
        s[t] += add;
        __syncthreads();
    }
    int run = (t == 0) ? 0 : s[t - 1];
    for (int i = 0; i < chunk; i++) {
        int idx = base + i;
        if (idx < NN) {
            g_offsets[idx] = run;
            run += g_counts[idx];
        }
    }
}

__global__ void k_scatter(const int* __restrict__ dst) {
    int e = blockIdx.x * blockDim.x + threadIdx.x;
    if (e < NE) {
        g_edge_ids[g_offsets[dst[e]] + g_pos[e]] = e;
    }
}

// ---------------- warp-per-node segment mean (4x unroll, streaming) ---------
__global__ void k_aggregate(const float* __restrict__ edge_attrs) {
    int warp = threadIdx.x >> 5;
    int lane = threadIdx.x & 31;
    int node = blockIdx.x * (blockDim.x >> 5) + warp;
    if (node >= NN) return;

    int start = g_offsets[node];
    int deg   = g_counts[node];

    float4 a0 = make_float4(0.f, 0.f, 0.f, 0.f);
    float4 a1 = make_float4(0.f, 0.f, 0.f, 0.f);
    float4 a2 = make_float4(0.f, 0.f, 0.f, 0.f);
    float4 a3 = make_float4(0.f, 0.f, 0.f, 0.f);
    int i = 0;
    for (; i + 3 < deg; i += 4) {
        int e0 = g_edge_ids[start + i];
        int e1 = g_edge_ids[start + i + 1];
        int e2 = g_edge_ids[start + i + 2];
        int e3 = g_edge_ids[start + i + 3];
        float4 v0 = ldcs4(edge_attrs + (size_t)e0 * D + lane * 4);
        float4 v1 = ldcs4(edge_attrs + (size_t)e1 * D + lane * 4);
        float4 v2 = ldcs4(edge_attrs + (size_t)e2 * D + lane * 4);
        float4 v3 = ldcs4(edge_attrs + (size_t)e3 * D + lane * 4);
        a0.x += v0.x; a0.y += v0.y; a0.z += v0.z; a0.w += v0.w;
        a1.x += v1.x; a1.y += v1.y; a1.z += v1.z; a1.w += v1.w;
        a2.x += v2.x; a2.y += v2.y; a2.z += v2.z; a2.w += v2.w;
        a3.x += v3.x; a3.y += v3.y; a3.z += v3.z; a3.w += v3.w;
    }
    for (; i < deg; i++) {
        int e0 = g_edge_ids[start + i];
        float4 v0 = ldcs4(edge_attrs + (size_t)e0 * D + lane * 4);
        a0.x += v0.x; a0.y += v0.y; a0.z += v0.z; a0.w += v0.w;
    }
    float inv = (deg > 0) ? (1.0f / (float)deg) : 0.0f;
    float4 r;
    r.x = (a0.x + a1.x + a2.x + a3.x) * inv;
    r.y = (a0.y + a1.y + a2.y + a3.y) * inv;
    r.z = (a0.z + a1.z + a2.z + a3.z) * inv;
    r.w = (a0.w + a1.w + a2.w + a3.w) * inv;
    *((float4*)(g_agg + (size_t)node * D) + lane) = r;
}

// ---------------- fused 2-layer MLP with mma.sync bf16-split ----------------
#define SM_SA(s) ((s) * 16384)
#define SM_SB(s) (32768 + (s) * 16384)
#define SM_A2 65536
#define SM_B2 131072
#define MLP_SMEM 196608

__device__ __forceinline__ void mma_block(const char* sm, uint32_t abase,
                                          uint32_t bbase, int KT, int kt,
                                          int wm, int wn, int lane,
                                          float Dm[2][8][4]) {
    uint4 ah[2], al[2];
#pragma unroll
    for (int mt = 0; mt < 2; mt++) {
        const uint4* p = (const uint4*)(sm + abase +
            (uint32_t)((((wm * 2 + mt) * KT + kt) * 32 + lane) * 32));
        ah[mt] = p[0];
        al[mt] = p[1];
    }
#pragma unroll
    for (int nt = 0; nt < 8; nt++) {
        uint4 b = *(const uint4*)(sm + bbase +
            (uint32_t)((((wn * 8 + nt) * KT + kt) * 32 + lane) * 16));
#pragma unroll
        for (int mt = 0; mt < 2; mt++) {
            mma_bf16(Dm[mt][nt], ah[mt].x, ah[mt].y, ah[mt].z, ah[mt].w, b.x, b.y);
            mma_bf16(Dm[mt][nt], ah[mt].x, ah[mt].y, ah[mt].z, ah[mt].w, b.z, b.w);
            mma_bf16(Dm[mt][nt], al[mt].x, al[mt].y, al[mt].z, al[mt].w, b.x, b.y);
        }
    }
}

__global__ void __launch_bounds__(256, 1)
k_mlp(const float* __restrict__ agg, const float* __restrict__ node,
      const float* __restrict__ c0, const float* __restrict__ b2,
      float* __restrict__ out) {
    extern __shared__ char sm[];
    int tid = threadIdx.x, lane = tid & 31, wid = tid >> 5;
    int wm = wid >> 1, wn = wid & 1;
    int m0 = blockIdx.x * 128;

    int srow = tid >> 1;
    int skt  = tid & 1;
    int smt  = srow >> 4;
    int slan = (srow & 7) * 4;
    int srh  = (srow >> 3) & 1;
    int gm   = m0 + srow;
    bool mok = (gm < NN);

    float D1[2][8][4];
#pragma unroll
    for (int a = 0; a < 2; a++)
#pragma unroll
        for (int b = 0; b < 8; b++)
#pragma unroll
            for (int q = 0; q < 4; q++) D1[a][b][q] = 0.f;

    float4 va[4];
    uint4  vb[4];
    {
        const float* src = agg;
        int kc = skt * 16;
#pragma unroll
        for (int q = 0; q < 4; q++)
            va[q] = mok ? *(const float4*)(src + (size_t)gm * D + kc + q * 4)
                        : make_float4(0.f, 0.f, 0.f, 0.f);
#pragma unroll
        for (int q = 0; q < 4; q++) vb[q] = g_W1f[tid + q * 256];
    }

    for (int s = 0; s < 8; s++) {
        int buf = s & 1;
        {
            float xs[16];
#pragma unroll
            for (int q = 0; q < 4; q++) {
                xs[q * 4 + 0] = va[q].x; xs[q * 4 + 1] = va[q].y;
                xs[q * 4 + 2] = va[q].z; xs[q * 4 + 3] = va[q].w;
            }
            uint32_t abase = SM_SA(buf) + (uint32_t)(((smt * 2 + skt) * 32) * 32);
#pragma unroll
            for (int p = 0; p < 8; p++) {
                uint32_t hi, lo;
                split_pair(xs[2 * p], xs[2 * p + 1], hi, lo);
                int c = p & 3, j = p >> 2;
                uint32_t off = abase + (uint32_t)((slan + c) * 32 + (srh + 2 * j) * 4);
                *(uint32_t*)(sm + off)      = hi;
                *(uint32_t*)(sm + off + 16) = lo;
            }
            uint4* bdst = (uint4*)(sm + SM_SB(buf));
#pragma unroll
            for (int q = 0; q < 4; q++) bdst[tid + q * 256] = vb[q];
        }
        __syncthreads();
        if (s == 0) {
            uint4* b2dst = (uint4*)(sm + SM_B2);
            for (int q = 0; q < 16; q++) b2dst[tid + q * 256] = g_W2f[tid + q * 256];
        }
        if (s < 7) {
            const float* src = (s + 1 < 4) ? agg : node;
            int kc = ((s + 1) & 3) * 32 + skt * 16;
#pragma unroll
            for (int q = 0; q < 4; q++)
                va[q] = mok ? *(const float4*)(src + (size_t)gm * D + kc + q * 4)
                            : make_float4(0.f, 0.f, 0.f, 0.f);
#pragma unroll
            for (int q = 0; q < 4; q++) vb[q] = g_W1f[(s + 1) * 1024 + tid + q * 256];
        }
        mma_block(sm, SM_SA(buf), SM_SB(buf), 2, 0, wm, wn, lane, D1);
        mma_block(sm, SM_SA(buf), SM_SB(buf), 2, 1, wm, wn, lane, D1);
    }

    // epilogue-1: h = relu(D1 + c0) -> frag-major A2 (bf16 hi/lo)
    {
        int c = lane & 3;
#pragma unroll
        for (int mt = 0; mt < 2; mt++) {
#pragma unroll
            for (int nt = 0; nt < 8; nt++) {
                int col = wn * 64 + nt * 8 + 2 * c;
                float2 cv = *(const float2*)(c0 + col);
                float h0 = fmaxf(D1[mt][nt][0] + cv.x, 0.f);
                float h1 = fmaxf(D1[mt][nt][1] + cv.y, 0.f);
                float h2 = fmaxf(D1[mt][nt][2] + cv.x, 0.f);
                float h3 = fmaxf(D1[mt][nt][3] + cv.y, 0.f);
                uint32_t hi0, lo0, hi1, lo1;
                split_pair(h0, h1, hi0, lo0);
                split_pair(h2, h3, hi1, lo1);
                int mtile2 = wm * 2 + mt;
                int ktile2 = wn * 4 + (nt >> 1);
                int j2 = nt & 1;
                uint32_t base = SM_A2 +
                    (uint32_t)(((mtile2 * 8 + ktile2) * 32 + lane) * 32);
                *(uint32_t*)(sm + base + (0 + 2 * j2) * 4)      = hi0;
                *(uint32_t*)(sm + base + (0 + 2 * j2) * 4 + 16) = lo0;
                *(uint32_t*)(sm + base + (1 + 2 * j2) * 4)      = hi1;
                *(uint32_t*)(sm + base + (1 + 2 * j2) * 4 + 16) = lo1;
            }
        }
    }
    __syncthreads();

    float D2[2][8][4];
#pragma unroll
    for (int a = 0; a < 2; a++)
#pragma unroll
        for (int b = 0; b < 8; b++)
#pragma unroll
            for (int q = 0; q < 4; q++) D2[a][b][q] = 0.f;
#pragma unroll
    for (int kt = 0; kt < 8; kt++)
        mma_block(sm, SM_A2, SM_B2, 8, kt, wm, wn, lane, D2);

    {
        int c = lane & 3, g = lane >> 2;
#pragma unroll
        for (int mt = 0; mt < 2; mt++) {
            int mrow = m0 + wm * 32 + mt * 16 + g;
#pragma unroll
            for (int nt = 0; nt < 8; nt++) {
                int col = wn * 64 + nt * 8 + 2 * c;
                float2 bv = *(const float2*)(b2 + col);
                if (mrow < NN) {
                    float2 o0 = make_float2(D2[mt][nt][0] + bv.x,
                                            D2[mt][nt][1] + bv.y);
                    *(float2*)(out + (size_t)mrow * D + col) = o0;
                }
                if (mrow + 8 < NN) {
                    float2 o1 = make_float2(D2[mt][nt][2] + bv.x,
                                            D2[mt][nt][3] + bv.y);
                    *(float2*)(out + (size_t)(mrow + 8) * D + col) = o1;
                }
            }
        }
    }
}

// ---------------- launch -----------------------------------------------------
extern "C" void kernel_launch(void* const* d_in, const int* in_sizes, int n_in,
                              void* d_out, int out_size) {
    const float* edge_attrs = (const float*)d_in[0];
    const float* node_attrs = (const float*)d_in[1];
    const float* gattr      = (const float*)d_in[2];
    const float* W1         = (const float*)d_in[3];
    const float* b1         = (const float*)d_in[4];
    const float* W2         = (const float*)d_in[5];
    const float* b2         = (const float*)d_in[6];
    const int*   edge_dst   = (const int*)d_in[7];
    float*       out        = (float*)d_out;

    float* agg_p; cudaGetSymbolAddress((void**)&agg_p, g_agg);
    float* c0_p;  cudaGetSymbolAddress((void**)&c0_p,  g_c0);

    cudaFuncSetAttribute(k_mlp, cudaFuncAttributeMaxDynamicSharedMemorySize,
                         MLP_SMEM);

    k_init<<<245, 256>>>(gattr, W1, b1, W2);
    k_count_pos<<<(NE + 255) / 256, 256>>>(edge_dst);
    k_scan<<<1, 1024>>>();
    k_scatter<<<(NE + 255) / 256, 256>>>(edge_dst);
    k_aggregate<<<(NN + 7) / 8, 256>>>(edge_attrs);

    int mb = (NN + 127) / 128;
    k_mlp<<<mb, 256, MLP_SMEM>>>(agg_p, node_attrs, c0_p, b2, out);
}